// round 14
// baseline (speedup 1.0000x reference)
#include <cuda_runtime.h>
#include <cstdint>

// KANLinear fused as one tf32 mma.sync GEMM:
//   out[32768,256] = A[32768,2304] @ W[256,2304]^T
//   A = [ silu(x) | b_splines(x) flat ],  W = [ base_weight | spline_weight*scaler ]
// Round 14: merged K=64 chunks (36 barriers), vectorized A fragment path
// (LDS.64 loads / STS.64 stores, conflict-free swizzled layout), B-fragment
// prefetch. 512 CTAs BM=64 x BN=256, TPB=256, 2 CTAs/SM.

#define TPB 256
#define NMERGE 36
// A layout: plane(mf,ks,rh) of 66 words; slot off = (l&15)*2 + (l>>4)*34 + kh
#define A_TOT (4 * 8 * 2 * 66)     // 4224 words per buffer
#define X_STRIDE 65
#define X_WORDS (64 * X_STRIDE)    // 4160 words per buffer
#define SMEM_BYTES ((2 * A_TOT + 2 * X_WORDS) * 4)   // 67072

// W fragments: [mchunk 0..35][nfg 0..31][ks 0..7][lane 0..31] -> float2 (b0,b1)
__device__ float2 g_wfrag[NMERGE * 32 * 8 * 32];

static __device__ __forceinline__ float tf32_rn(float f) {
    uint32_t u;
    asm("cvt.rna.tf32.f32 %0, %1;" : "=r"(u) : "f"(f));
    return __uint_as_float(u);
}

// ---------------- pre-kernel: build W fragments ----------------
static __device__ __forceinline__ float waug(
    int n, int K, const float* __restrict__ BW, const float* __restrict__ SW,
    const float* __restrict__ SS)
{
    if (K < 256) return tf32_rn(BW[(size_t)n * 256 + K]);
    int F = K - 256;
    int f = F >> 3, cf = F & 7;
    return tf32_rn(SW[((size_t)n * 256 + f) * 8 + cf] * SS[(size_t)n * 256 + f]);
}

__global__ void wfrag_kernel(const float* __restrict__ BW,
                             const float* __restrict__ SW,
                             const float* __restrict__ SS)
{
    int idx = blockIdx.x * 256 + threadIdx.x;          // 0 .. 294911
    int lane = idx & 31;
    int ks   = (idx >> 5) & 7;
    int nfg  = (idx >> 8) & 31;
    int c    = idx >> 13;
    int n = nfg * 8 + (lane >> 2);
    int t = lane & 3;
    int K0 = c * 64 + ks * 8 + t;
    float2 v;
    v.x = waug(n, K0,     BW, SW, SS);
    v.y = waug(n, K0 + 4, BW, SW, SS);
    g_wfrag[idx] = v;
}

// ---------------- main kernel helpers ----------------
static __device__ __forceinline__ void stage_x(
    int c, float* __restrict__ sX, int rbase, int tid, const float* __restrict__ X)
{
    if (c >= NMERGE) return;
    if (c < 4) {
        // silu merged chunk: X[row][c*64 .. +64), 64 rows; each line read once
        const int row = tid & 63, seg = tid >> 6;       // seg 0..3: 16 k each
        const float4* p = reinterpret_cast<const float4*>(
            X + (size_t)(rbase + row) * 256 + c * 64 + seg * 16);
        float4 a = p[0], b = p[1], d = p[2], e = p[3];
        const int k0 = seg * 16;
        sX[(k0 +  0) * X_STRIDE + row] = a.x;
        sX[(k0 +  1) * X_STRIDE + row] = a.y;
        sX[(k0 +  2) * X_STRIDE + row] = a.z;
        sX[(k0 +  3) * X_STRIDE + row] = a.w;
        sX[(k0 +  4) * X_STRIDE + row] = b.x;
        sX[(k0 +  5) * X_STRIDE + row] = b.y;
        sX[(k0 +  6) * X_STRIDE + row] = b.z;
        sX[(k0 +  7) * X_STRIDE + row] = b.w;
        sX[(k0 +  8) * X_STRIDE + row] = d.x;
        sX[(k0 +  9) * X_STRIDE + row] = d.y;
        sX[(k0 + 10) * X_STRIDE + row] = d.z;
        sX[(k0 + 11) * X_STRIDE + row] = d.w;
        sX[(k0 + 12) * X_STRIDE + row] = e.x;
        sX[(k0 + 13) * X_STRIDE + row] = e.y;
        sX[(k0 + 14) * X_STRIDE + row] = e.z;
        sX[(k0 + 15) * X_STRIDE + row] = e.w;
    } else {
        // spline merged chunk: 8 features per row (2 float4 per row)
        if (tid < 128) {
            const int row = tid & 63, half = tid >> 6;
            float4 a = *reinterpret_cast<const float4*>(
                X + (size_t)(rbase + row) * 256 + (c - 4) * 8 + half * 4);
            sX[(half * 4 + 0) * X_STRIDE + row] = a.x;
            sX[(half * 4 + 1) * X_STRIDE + row] = a.y;
            sX[(half * 4 + 2) * X_STRIDE + row] = a.z;
            sX[(half * 4 + 3) * X_STRIDE + row] = a.w;
        }
    }
}

static __device__ __forceinline__ void gen_a(
    int c, float* __restrict__ sA, const float* __restrict__ sX, int tid,
    const float* __restrict__ sg,
    const float (*__restrict__ siL)[10], const float (*__restrict__ siR)[10])
{
    if (c >= NMERGE) return;
    const int r  = tid & 63;
    const int h  = tid >> 6;             // 0..3
    const int mf = r >> 4, rh = (r >> 3) & 1, g7 = r & 7;
#pragma unroll
    for (int kk = 0; kk < 2; ++kk) {
        const int kg = h + kk * 4;       // k group 0..7 (8 k each)
        float v[8];
        if (c < 4) {
#pragma unroll
            for (int u = 0; u < 8; ++u) {
                float x = sX[(kg * 8 + u) * X_STRIDE + r];
                v[u] = tf32_rn(__fdividef(x, 1.0f + __expf(-x)));
            }
        } else {
            const float x = sX[kg * X_STRIDE + r];
            float bs[11];
#pragma unroll
            for (int j = 0; j < 11; ++j)
                bs[j] = (x >= sg[j] && x < sg[j + 1]) ? 1.0f : 0.0f;
#pragma unroll
            for (int k = 1; k <= 3; ++k) {
#pragma unroll
                for (int j = 0; j < 10; ++j) {
                    if (j <= 10 - k)
                        bs[j] = (x - sg[j]) * siL[k - 1][j] * bs[j]
                              + (sg[j + k + 1] - x) * siR[k - 1][j] * bs[j + 1];
                }
            }
#pragma unroll
            for (int j = 0; j < 8; ++j) v[j] = tf32_rn(bs[j]);
        }
        float* base = sA + ((mf * 8 + kg) * 2 + rh) * 66;
#pragma unroll
        for (int t = 0; t < 4; ++t) {
            const int l = g7 * 4 + t;
            const int off = (l & 15) * 2 + (l >> 4) * 34;
            *reinterpret_cast<float2*>(base + off) = make_float2(v[t], v[t + 4]);
        }
    }
}

__global__ void __launch_bounds__(TPB, 2) kan_kernel(
    const float* __restrict__ X,    // [32768,256]
    const float* __restrict__ G,    // [12]
    float* __restrict__ OUT)        // [32768,256]
{
    extern __shared__ float sm[];
    float* sA  = sm;                      // 2 * A_TOT
    float* sXs = sm + 2 * A_TOT;          // 2 * X_WORDS
    __shared__ float s_g[12];
    __shared__ float s_iL[3][10];
    __shared__ float s_iR[3][10];

    const int tid  = threadIdx.x;
    const int wid  = tid >> 5;
    const int lane = tid & 31;

    if (tid < 12) s_g[tid] = G[tid];
    __syncthreads();
    if (tid < 30) {
        int k = tid / 10, j = tid % 10;   // k = order-1 (0..2)
        if (j <= 9 - k) {
            s_iL[k][j] = 1.0f / (s_g[j + k + 1] - s_g[j]);
            s_iR[k][j] = 1.0f / (s_g[j + k + 2] - s_g[j + 1]);
        }
    }
    __syncthreads();

    const int rbase  = blockIdx.x * 64;
    const int warp_n = wid;               // 8 n-warps (32 cols each)
    const int nfg0   = warp_n * 4;        // wfrag group base
    const int loff   = (lane & 15) * 2 + (lane >> 4) * 34;

    float acc[4][4][4];
#pragma unroll
    for (int mf = 0; mf < 4; ++mf)
#pragma unroll
        for (int nf = 0; nf < 4; ++nf)
#pragma unroll
            for (int rr = 0; rr < 4; ++rr) acc[mf][nf][rr] = 0.0f;

    // prologue
    stage_x(0, sXs,           rbase, tid, X);
    stage_x(1, sXs + X_WORDS, rbase, tid, X);
    __syncthreads();
    gen_a(0, sA, sXs, tid, s_g, s_iL, s_iR);
    __syncthreads();

    for (int c = 0; c < NMERGE; ++c) {
        stage_x(c + 2, sXs + (c & 1) * X_WORDS, rbase, tid, X);
        gen_a(c + 1, sA + ((c + 1) & 1) * A_TOT,
              sXs + ((c + 1) & 1) * X_WORDS, tid, s_g, s_iL, s_iR);

        const float* bufA = sA + (c & 1) * A_TOT;
        const float2* __restrict__ wf = g_wfrag + (size_t)c * (32 * 8 * 32);

        float2 bv[4];
#pragma unroll
        for (int nf = 0; nf < 4; ++nf)
            bv[nf] = wf[((nfg0 + nf) * 8 + 0) * 32 + lane];

#pragma unroll
        for (int ks = 0; ks < 8; ++ks) {
            float2 bvn[4];
            if (ks < 7) {
#pragma unroll
                for (int nf = 0; nf < 4; ++nf)
                    bvn[nf] = wf[((nfg0 + nf) * 8 + ks + 1) * 32 + lane];
            }
            uint32_t a0[4], a1[4], a2[4], a3[4];
#pragma unroll
            for (int mf = 0; mf < 4; ++mf) {
                const float* bb = bufA + (mf * 8 + ks) * 132;
                float2 p0 = *reinterpret_cast<const float2*>(bb + loff);
                float2 p1 = *reinterpret_cast<const float2*>(bb + 66 + loff);
                a0[mf] = __float_as_uint(p0.x); a2[mf] = __float_as_uint(p0.y);
                a1[mf] = __float_as_uint(p1.x); a3[mf] = __float_as_uint(p1.y);
            }
#pragma unroll
            for (int nf = 0; nf < 4; ++nf) {
                const uint32_t b0 = __float_as_uint(bv[nf].x);
                const uint32_t b1 = __float_as_uint(bv[nf].y);
#pragma unroll
                for (int mf = 0; mf < 4; ++mf) {
                    asm volatile(
                        "mma.sync.aligned.m16n8k8.row.col.f32.tf32.tf32.f32 "
                        "{%0,%1,%2,%3}, {%4,%5,%6,%7}, {%8,%9}, {%0,%1,%2,%3};"
                        : "+f"(acc[mf][nf][0]), "+f"(acc[mf][nf][1]),
                          "+f"(acc[mf][nf][2]), "+f"(acc[mf][nf][3])
                        : "r"(a0[mf]), "r"(a1[mf]), "r"(a2[mf]), "r"(a3[mf]),
                          "r"(b0), "r"(b1));
                }
            }
            if (ks < 7) {
#pragma unroll
                for (int nf = 0; nf < 4; ++nf) bv[nf] = bvn[nf];
            }
        }
        __syncthreads();
    }

    // ---------------- epilogue: registers -> GMEM ----------------
    const int g = lane >> 2, t = lane & 3;
    const int cbase = warp_n * 32;
#pragma unroll
    for (int mf = 0; mf < 4; ++mf) {
#pragma unroll
        for (int nf = 0; nf < 4; ++nf) {
            const int row = rbase + mf * 16 + g;
            const int col = cbase + nf * 8 + t * 2;
            float2 lo; lo.x = acc[mf][nf][0]; lo.y = acc[mf][nf][1];
            float2 hi; hi.x = acc[mf][nf][2]; hi.y = acc[mf][nf][3];
            *reinterpret_cast<float2*>(OUT + (size_t)row * 256 + col) = lo;
            *reinterpret_cast<float2*>(OUT + (size_t)(row + 8) * 256 + col) = hi;
        }
    }
}

extern "C" void kernel_launch(void* const* d_in, const int* in_sizes, int n_in,
                              void* d_out, int out_size) {
    const float* X  = (const float*)d_in[0];
    const float* BW = (const float*)d_in[1];
    const float* SW = (const float*)d_in[2];
    const float* SS = (const float*)d_in[3];
    const float* G  = (const float*)d_in[4];
    float* OUT = (float*)d_out;
    (void)in_sizes; (void)n_in; (void)out_size;

    wfrag_kernel<<<NMERGE * 32 * 8 * 32 / 256, 256>>>(BW, SW, SS);

    cudaFuncSetAttribute(kan_kernel, cudaFuncAttributeMaxDynamicSharedMemorySize,
                         SMEM_BYTES);
    kan_kernel<<<512, TPB, SMEM_BYTES>>>(X, G, OUT);
}